// round 5
// baseline (speedup 1.0000x reference)
#include <cuda_runtime.h>
#include <cuda_bf16.h>

// RepformerLayer: nf=1, nloc=1024, nnei=128, ng2=32, nd=32, nh=4
// One CTA per location i (1024 CTAs, 512 threads = 16 warps, 8 rows/warp).
// R4: cut L1/shared wavefronts — fused Q+K G2 sweep, register hacc (no ASUM),
//     H2S pad-5 (conflict-free), warp-private AS (b->c syncwarp only).
//
// Algebra:
//   g2_out = b_head + sum_h A_h @ P_h,  P_h = g2 @ W2_h,  W2_h = w_v_h @ w_head_h
//   h2_out[q][c] = sum_h weq[h] * sum_k A_h[q][k] * h2[k][c]   (register-accumulated)

#define NLOC 1024
#define NNEI 128
#define NG2  32
#define NH   4

#define INV_SQRT_ND 0.17677669529663687f   // 1/sqrt(32)
#define INV_SQRT3   0.57735026918962576f   // 1/sqrt(3)
#define ATTNW_SHIFT 20.0f

typedef unsigned long long u64;

__device__ __forceinline__ u64 pk2(float lo, float hi) {
    u64 r;
    asm("mov.b64 %0, {%1, %2};" : "=l"(r) : "f"(lo), "f"(hi));
    return r;
}
__device__ __forceinline__ void upk2(u64 v, float& lo, float& hi) {
    asm("mov.b64 {%0, %1}, %2;" : "=f"(lo), "=f"(hi) : "l"(v));
}
__device__ __forceinline__ void fma2(u64& d, u64 a, u64 b) {
    asm("fma.rn.f32x2 %0, %1, %2, %0;" : "+l"(d) : "l"(a), "l"(b));
}
__device__ __forceinline__ float hsum2(u64 v) {
    float lo, hi; upk2(v, lo, hi); return lo + hi;
}

// Precomputed W2[h][j][o] = sum_g w_v[j, g*4+h] * w_head[g*4+h, o]
__device__ float g_W2[NH][NG2][NG2];

__global__ void precompute_W2_kernel(const float* __restrict__ w_v,
                                     const float* __restrict__ w_head) {
    int t = blockIdx.x * blockDim.x + threadIdx.x;
    if (t >= NH * NG2 * NG2) return;
    int o = t & 31;
    int j = (t >> 5) & 31;
    int h = t >> 10;
    float s = 0.0f;
#pragma unroll
    for (int g = 0; g < 32; g++)
        s = fmaf(w_v[j * 128 + g * 4 + h], w_head[(g * 4 + h) * 32 + o], s);
    g_W2[h][j][o] = s;
}

// ---- shared memory layout (floats) ----
// G2   [128][32]   : 0      .. 4096
// QS   [128][36]   : 4096   .. 8704     (pad 36: conflict-free .128)
// KS   [128][36]   : 8704   .. 13312
// PS   [128][32]   : 13312  .. 17408
// AS   [128][128]  : 17408  .. 33792    (warp-private row blocks)
// H2S  [128][5]    : 33792  .. 34432    (pad 5: conflict-free strided scalar reads)
// SWS  [128]       : 34432  .. 34560
// MFS  [128]       : 34560  .. 34688
#define SM_FLOATS 34688

__global__ __launch_bounds__(512, 1)
void repformer_kernel(const float* __restrict__ g2,
                      const float* __restrict__ h2,
                      const float* __restrict__ sw,
                      const float* __restrict__ w_qk,
                      const float* __restrict__ b_head,
                      const float* __restrict__ w_eqhead,
                      const int*   __restrict__ nlist_mask,
                      float* __restrict__ out) {
    extern __shared__ float sm[];
    float* G2  = sm;
    float* QS  = sm + 4096;
    float* KS  = sm + 8704;
    float* PS  = sm + 13312;
    float* AS  = sm + 17408;
    float* H2S = sm + 33792;
    float* SWS = sm + 34432;
    float* MFS = sm + 34560;

    const int i    = blockIdx.x;
    const int tid  = threadIdx.x;
    const int lane = tid & 31;
    const int w    = tid >> 5;   // warp 0..15

    // ---- load tile ----
    {
        const float4* src = (const float4*)(g2 + (size_t)i * NNEI * NG2);
        float4* dst = (float4*)G2;
        for (int v = tid; v < NNEI * NG2 / 4; v += 512) dst[v] = src[v];
        if (tid < NNEI) {
            int n = tid;
            size_t base = ((size_t)i * NNEI + n);
            H2S[n * 5 + 0] = h2[base * 3 + 0];
            H2S[n * 5 + 1] = h2[base * 3 + 1];
            H2S[n * 5 + 2] = h2[base * 3 + 2];
            SWS[n] = sw[base];
            MFS[n] = nlist_mask[base] ? 1.0f : 0.0f;
        }
    }
    __syncthreads();

    // persistent per-warp accumulators
    u64 outAcc[8];                     // g2_out: rows w*8..+7, col = lane (packed even/odd-k)
    float hacc0[8], hacc1[8], hacc2[8]; // h2_out partials: rows w*8..+7, lane holds k-subset sum
#pragma unroll
    for (int r = 0; r < 8; r++) {
        outAcc[r] = 0ull;
        hacc0[r] = hacc1[r] = hacc2[r] = 0.0f;
    }

#pragma unroll 1
    for (int h = 0; h < NH; h++) {
        const float weq = w_eqhead[h];

        // ============ phase a1: fused Q,K projection (one G2 sweep, half-split weights) ====
        // thread: column = lane, rows = w + 16*r (r=0..7)
        {
            u64 aq[8], ak[8];
#pragma unroll
            for (int r = 0; r < 8; r++) { aq[r] = 0ull; ak[r] = 0ull; }
#pragma unroll
            for (int half = 0; half < 2; half++) {
                u64 wq[8], wk[8];
#pragma unroll
                for (int t = 0; t < 8; t++) {
                    int j = half * 16 + 2 * t;
                    wq[t] = pk2(__ldg(&w_qk[j * 256 + lane * 8 + h]),
                                __ldg(&w_qk[(j + 1) * 256 + lane * 8 + h]));
                    wk[t] = pk2(__ldg(&w_qk[j * 256 + lane * 8 + 4 + h]),
                                __ldg(&w_qk[(j + 1) * 256 + lane * 8 + 4 + h]));
                }
#pragma unroll
                for (int j4 = 0; j4 < 4; j4++) {
#pragma unroll
                    for (int r = 0; r < 8; r++) {
                        ulonglong2 g = *(const ulonglong2*)(G2 + (w + 16 * r) * 32 + half * 16 + j4 * 4);
                        fma2(aq[r], g.x, wq[2 * j4]);
                        fma2(aq[r], g.y, wq[2 * j4 + 1]);
                        fma2(ak[r], g.x, wk[2 * j4]);
                        fma2(ak[r], g.y, wk[2 * j4 + 1]);
                    }
                }
            }
#pragma unroll
            for (int r = 0; r < 8; r++) {
                QS[(w + 16 * r) * 36 + lane] = hsum2(aq[r]) * INV_SQRT_ND;
                KS[(w + 16 * r) * 36 + lane] = hsum2(ak[r]);
            }
        }
        // ============ phase a2: PS = g2 @ W2_h ============
        {
            u64 ap[8];
#pragma unroll
            for (int r = 0; r < 8; r++) ap[r] = 0ull;
#pragma unroll
            for (int half = 0; half < 2; half++) {
                u64 wp[8];
#pragma unroll
                for (int t = 0; t < 8; t++) {
                    int j = half * 16 + 2 * t;
                    wp[t] = pk2(g_W2[h][j][lane], g_W2[h][j + 1][lane]);
                }
#pragma unroll
                for (int j4 = 0; j4 < 4; j4++) {
#pragma unroll
                    for (int r = 0; r < 8; r++) {
                        ulonglong2 g = *(const ulonglong2*)(G2 + (w + 16 * r) * 32 + half * 16 + j4 * 4);
                        fma2(ap[r], g.x, wp[2 * j4]);
                        fma2(ap[r], g.y, wp[2 * j4 + 1]);
                    }
                }
            }
#pragma unroll
            for (int r = 0; r < 8; r++)
                PS[(w + 16 * r) * 32 + lane] = hsum2(ap[r]);
        }
        __syncthreads();

        // ============ phase b: QK^T + scaling + softmax + masking ============
        // warp w owns rows w*8..w*8+7; lane owns k = lane + 32*m
        {
            const int qbase = w * 8;

            float hk0[4], hk1[4], hk2[4], swk[4], kc[4];
#pragma unroll
            for (int m = 0; m < 4; m++) {
                int k = lane + 32 * m;
                hk0[m] = H2S[k * 5 + 0];
                hk1[m] = H2S[k * 5 + 1];
                hk2[m] = H2S[k * 5 + 2];
                swk[m] = SWS[k];
                kc[m]  = swk[m] * MFS[k];
            }

            float acc[8][4];
#pragma unroll
            for (int r = 0; r < 8; r++)
#pragma unroll
                for (int m = 0; m < 4; m++) acc[r][m] = 0.0f;

#pragma unroll
            for (int d4 = 0; d4 < 8; d4++) {
                float4 kvv[4];
#pragma unroll
                for (int m = 0; m < 4; m++)
                    kvv[m] = *(const float4*)(KS + (lane + 32 * m) * 36 + d4 * 4);
#pragma unroll
                for (int r = 0; r < 8; r++) {
                    float4 qv = *(const float4*)(QS + (qbase + r) * 36 + d4 * 4);
#pragma unroll
                    for (int m = 0; m < 4; m++) {
                        acc[r][m] = fmaf(qv.x, kvv[m].x, acc[r][m]);
                        acc[r][m] = fmaf(qv.y, kvv[m].y, acc[r][m]);
                        acc[r][m] = fmaf(qv.z, kvv[m].z, acc[r][m]);
                        acc[r][m] = fmaf(qv.w, kvv[m].w, acc[r][m]);
                    }
                }
            }

#pragma unroll
            for (int r = 0; r < 8; r++) {
                const int q = qbase + r;
                const float hq0 = H2S[q * 5 + 0];
                const float hq1 = H2S[q * 5 + 1];
                const float hq2 = H2S[q * 5 + 2];
                const float swq = SWS[q];
                const float mq  = MFS[q];

                float hh[4], val[4];
#pragma unroll
                for (int m = 0; m < 4; m++) {
                    hh[m] = fmaf(hq0, hk0[m], fmaf(hq1, hk1[m], hq2 * hk2[m]));
                    float a = acc[r][m] * hh[m];
                    val[m] = (a + ATTNW_SHIFT) * swq * swk[m] - ATTNW_SHIFT;
                }
                float mx = fmaxf(fmaxf(val[0], val[1]), fmaxf(val[2], val[3]));
#pragma unroll
                for (int s = 16; s > 0; s >>= 1)
                    mx = fmaxf(mx, __shfl_xor_sync(0xffffffffu, mx, s));
                float ssum = 0.0f;
#pragma unroll
                for (int m = 0; m < 4; m++) {
                    val[m] = __expf(val[m] - mx);
                    ssum += val[m];
                }
#pragma unroll
                for (int s = 16; s > 0; s >>= 1)
                    ssum += __shfl_xor_sync(0xffffffffu, ssum, s);
                const float rowc = __frcp_rn(ssum) * swq * mq * INV_SQRT3;

                float hr0 = 0.0f, hr1 = 0.0f, hr2 = 0.0f;
#pragma unroll
                for (int m = 0; m < 4; m++) {
                    float A = val[m] * rowc * kc[m] * hh[m];
                    AS[q * 128 + lane + 32 * m] = A;
                    hr0 = fmaf(A, hk0[m], hr0);
                    hr1 = fmaf(A, hk1[m], hr1);
                    hr2 = fmaf(A, hk2[m], hr2);
                }
                hacc0[r] = fmaf(weq, hr0, hacc0[r]);
                hacc1[r] = fmaf(weq, hr1, hacc1[r]);
                hacc2[r] = fmaf(weq, hr2, hacc2[r]);
            }
        }
        __syncwarp();   // AS is warp-private: cross-lane STS->LDS visibility only

        // ============ phase c: outAcc[r] += sum_k AS[row][k] * PS[k][lane] (FFMA2) ============
        {
            const int rowbase = w * 8;
#pragma unroll 4
            for (int k4 = 0; k4 < 32; k4++) {
                float p0 = PS[(k4 * 4 + 0) * 32 + lane];
                float p1 = PS[(k4 * 4 + 1) * 32 + lane];
                float p2 = PS[(k4 * 4 + 2) * 32 + lane];
                float p3 = PS[(k4 * 4 + 3) * 32 + lane];
                u64 pA = pk2(p0, p1);
                u64 pB = pk2(p2, p3);
#pragma unroll
                for (int r = 0; r < 8; r++) {
                    ulonglong2 a = *(const ulonglong2*)(AS + (rowbase + r) * 128 + k4 * 4);
                    fma2(outAcc[r], a.x, pA);
                    fma2(outAcc[r], a.y, pB);
                }
            }
        }
        __syncthreads();   // QS/KS/PS reused next head
    }

    // ---- epilogue: g2_out ----
    {
        const float b = b_head[lane];
        const int rowbase = w * 8;
#pragma unroll
        for (int r = 0; r < 8; r++) {
            int q = rowbase + r;
            out[((size_t)i * NNEI + q) * 32 + lane] = hsum2(outAcc[r]) + b;
        }
    }

    // ---- epilogue: h2_out via warp reduction of hacc ----
    {
        float* oh = out + (size_t)NLOC * NNEI * 32;
#pragma unroll
        for (int r = 0; r < 8; r++) {
            float s0 = hacc0[r], s1 = hacc1[r], s2 = hacc2[r];
#pragma unroll
            for (int s = 16; s > 0; s >>= 1) {
                s0 += __shfl_xor_sync(0xffffffffu, s0, s);
                s1 += __shfl_xor_sync(0xffffffffu, s1, s);
                s2 += __shfl_xor_sync(0xffffffffu, s2, s);
            }
            if (lane == 0) {
                int q = w * 8 + r;
                size_t base = ((size_t)i * NNEI + q) * 3;
                oh[base + 0] = s0;
                oh[base + 1] = s1;
                oh[base + 2] = s2;
            }
        }
    }
}

extern "C" void kernel_launch(void* const* d_in, const int* in_sizes, int n_in,
                              void* d_out, int out_size) {
    const float* g2       = (const float*)d_in[0];
    const float* h2       = (const float*)d_in[1];
    const float* sw       = (const float*)d_in[2];
    const float* w_qk     = (const float*)d_in[3];
    const float* w_v      = (const float*)d_in[4];
    const float* w_head   = (const float*)d_in[5];
    const float* b_head   = (const float*)d_in[6];
    const float* w_eqhead = (const float*)d_in[7];
    const int*   nmask    = (const int*)d_in[8];
    float* out = (float*)d_out;

    precompute_W2_kernel<<<16, 256>>>(w_v, w_head);

    const size_t smem = (size_t)SM_FLOATS * sizeof(float);   // ~135.5 KB
    cudaFuncSetAttribute(repformer_kernel,
                         cudaFuncAttributeMaxDynamicSharedMemorySize, (int)smem);
    repformer_kernel<<<NLOC, 512, smem>>>(g2, h2, sw, w_qk, b_head, w_eqhead, nmask, out);
}

// round 6
// speedup vs baseline: 1.1966x; 1.1966x over previous
#include <cuda_runtime.h>
#include <cuda_bf16.h>

// RepformerLayer: nf=1, nloc=1024, nnei=128, ng2=32, nd=32, nh=4
// One CTA per location i (1024 CTAs, 512 threads = 16 warps, 8 rows/warp).
// R5: R3 base + phase-c multi-address A-gather (4 lane-groups x k-quarters),
//     bank-tuned AS (stride 144, group offset 36) and PS ([kc][g][40]) layouts,
//     lane owns 4 o-columns, end-of-kernel bfly reduce. H2S pad-5, syncwarp b->c.
//
// Algebra:
//   g2_out = b_head + sum_h A_h @ P_h,  P_h = g2 @ W2_h,  W2_h = w_v_h @ w_head_h
//   h2_out = (sum_h weq[h] * A_h) @ h2   (ASUM in smem)

#define NLOC 1024
#define NNEI 128
#define NG2  32
#define NH   4

#define INV_SQRT_ND 0.17677669529663687f   // 1/sqrt(32)
#define INV_SQRT3   0.57735026918962576f   // 1/sqrt(3)
#define ATTNW_SHIFT 20.0f

typedef unsigned long long u64;

__device__ __forceinline__ u64 pk2(float lo, float hi) {
    u64 r;
    asm("mov.b64 %0, {%1, %2};" : "=l"(r) : "f"(lo), "f"(hi));
    return r;
}
__device__ __forceinline__ void upk2(u64 v, float& lo, float& hi) {
    asm("mov.b64 {%0, %1}, %2;" : "=f"(lo), "=f"(hi) : "l"(v));
}
__device__ __forceinline__ void fma2(u64& d, u64 a, u64 b) {
    asm("fma.rn.f32x2 %0, %1, %2, %0;" : "+l"(d) : "l"(a), "l"(b));
}
__device__ __forceinline__ float hsum2(u64 v) {
    float lo, hi; upk2(v, lo, hi); return lo + hi;
}

// Precomputed W2[h][j][o] = sum_g w_v[j, g*4+h] * w_head[g*4+h, o]
__device__ float g_W2[NH][NG2][NG2];

__global__ void precompute_W2_kernel(const float* __restrict__ w_v,
                                     const float* __restrict__ w_head) {
    int t = blockIdx.x * blockDim.x + threadIdx.x;
    if (t >= NH * NG2 * NG2) return;
    int o = t & 31;
    int j = (t >> 5) & 31;
    int h = t >> 10;
    float s = 0.0f;
#pragma unroll
    for (int g = 0; g < 32; g++)
        s = fmaf(w_v[j * 128 + g * 4 + h], w_head[(g * 4 + h) * 32 + o], s);
    g_W2[h][j][o] = s;
}

// ---- shared memory layout (floats) ----
// G2   [128][32]    : 0      .. 4096
// QS   [128][36]    : 4096   .. 8704     (pad 36: conflict-free .128)
// KS   [128][36]    : 8704   .. 13312
// PS   [32][4][40]  : 13312  .. 18432    (PS[k][o] at (k%32)*160 + (k/32)*40 + o)
// AS   [128][144]   : 18432  .. 36864    (A[q][k] at q*144 + (k/32)*36 + (k%32))
// ASUM [128][132]   : 36864  .. 53760
// H2S  [128][5]     : 53760  .. 54400
// SWS  [128]        : 54400  .. 54528
// MFS  [128]        : 54528  .. 54656
#define SM_FLOATS 54656

__global__ __launch_bounds__(512, 1)
void repformer_kernel(const float* __restrict__ g2,
                      const float* __restrict__ h2,
                      const float* __restrict__ sw,
                      const float* __restrict__ w_qk,
                      const float* __restrict__ b_head,
                      const float* __restrict__ w_eqhead,
                      const int*   __restrict__ nlist_mask,
                      float* __restrict__ out) {
    extern __shared__ float sm[];
    float* G2   = sm;
    float* QS   = sm + 4096;
    float* KS   = sm + 8704;
    float* PS   = sm + 13312;
    float* AS   = sm + 18432;
    float* ASUM = sm + 36864;
    float* H2S  = sm + 53760;
    float* SWS  = sm + 54400;
    float* MFS  = sm + 54528;

    const int i    = blockIdx.x;
    const int tid  = threadIdx.x;
    const int lane = tid & 31;
    const int w    = tid >> 5;   // warp 0..15
    const int g    = lane >> 3;  // phase-c k-quarter group
    const int s    = lane & 7;

    // ---- load tile ----
    {
        const float4* src = (const float4*)(g2 + (size_t)i * NNEI * NG2);
        float4* dst = (float4*)G2;
        for (int v = tid; v < NNEI * NG2 / 4; v += 512) dst[v] = src[v];
        if (tid < NNEI) {
            int n = tid;
            size_t base = ((size_t)i * NNEI + n);
            H2S[n * 5 + 0] = h2[base * 3 + 0];
            H2S[n * 5 + 1] = h2[base * 3 + 1];
            H2S[n * 5 + 2] = h2[base * 3 + 2];
            SWS[n] = sw[base];
            MFS[n] = nlist_mask[base] ? 1.0f : 0.0f;
        }
    }
    __syncthreads();

    // phase-c persistent accumulators: warp w owns rows w*8..+7;
    // lane (g,s) owns o in {s,s+8} (accO0) and {s+16,s+24} (accO1), k in [g*32, g*32+32)
    u64 accO0[8], accO1[8];
#pragma unroll
    for (int r = 0; r < 8; r++) { accO0[r] = 0ull; accO1[r] = 0ull; }

#pragma unroll 1
    for (int h = 0; h < NH; h++) {
        const float weq = w_eqhead[h];

        // ============ phase a: QS = g2@Wq/sqrt(nd), KS = g2@Wk, PS = g2@W2_h ============
        // thread: column = lane, rows = w + 16*r (r=0..7). Packed weights + FFMA2.
#pragma unroll 1
        for (int m = 0; m < 3; m++) {
            u64 wreg[16];
            if (m == 0) {
#pragma unroll
                for (int t = 0; t < 16; t++)
                    wreg[t] = pk2(__ldg(&w_qk[(2 * t) * 256 + lane * 8 + h]),
                                  __ldg(&w_qk[(2 * t + 1) * 256 + lane * 8 + h]));
            } else if (m == 1) {
#pragma unroll
                for (int t = 0; t < 16; t++)
                    wreg[t] = pk2(__ldg(&w_qk[(2 * t) * 256 + lane * 8 + 4 + h]),
                                  __ldg(&w_qk[(2 * t + 1) * 256 + lane * 8 + 4 + h]));
            } else {
#pragma unroll
                for (int t = 0; t < 16; t++)
                    wreg[t] = pk2(g_W2[h][2 * t][lane], g_W2[h][2 * t + 1][lane]);
            }
            u64 acc[8];
#pragma unroll
            for (int r = 0; r < 8; r++) acc[r] = 0ull;
#pragma unroll
            for (int j4 = 0; j4 < 8; j4++) {
#pragma unroll
                for (int r = 0; r < 8; r++) {
                    ulonglong2 gv = *(const ulonglong2*)(G2 + (w + 16 * r) * 32 + j4 * 4);
                    fma2(acc[r], gv.x, wreg[2 * j4]);
                    fma2(acc[r], gv.y, wreg[2 * j4 + 1]);
                }
            }
            if (m == 0) {
#pragma unroll
                for (int r = 0; r < 8; r++)
                    QS[(w + 16 * r) * 36 + lane] = hsum2(acc[r]) * INV_SQRT_ND;
            } else if (m == 1) {
#pragma unroll
                for (int r = 0; r < 8; r++)
                    KS[(w + 16 * r) * 36 + lane] = hsum2(acc[r]);
            } else {
#pragma unroll
                for (int r = 0; r < 8; r++) {
                    int row = w + 16 * r;
                    PS[(row & 31) * 160 + (row >> 5) * 40 + lane] = hsum2(acc[r]);
                }
            }
        }
        __syncthreads();

        // ============ phase b: QK^T + scaling + softmax + masking ============
        // warp w owns rows w*8..w*8+7; lane owns k = lane + 32*m
        {
            const int qbase = w * 8;

            float hk0[4], hk1[4], hk2[4], swk[4], kc[4];
#pragma unroll
            for (int m = 0; m < 4; m++) {
                int k = lane + 32 * m;
                hk0[m] = H2S[k * 5 + 0];
                hk1[m] = H2S[k * 5 + 1];
                hk2[m] = H2S[k * 5 + 2];
                swk[m] = SWS[k];
                kc[m]  = swk[m] * MFS[k];
            }

            float acc[8][4];
#pragma unroll
            for (int r = 0; r < 8; r++)
#pragma unroll
                for (int m = 0; m < 4; m++) acc[r][m] = 0.0f;

#pragma unroll
            for (int d4 = 0; d4 < 8; d4++) {
                float4 kvv[4];
#pragma unroll
                for (int m = 0; m < 4; m++)
                    kvv[m] = *(const float4*)(KS + (lane + 32 * m) * 36 + d4 * 4);
#pragma unroll
                for (int r = 0; r < 8; r++) {
                    float4 qv = *(const float4*)(QS + (qbase + r) * 36 + d4 * 4);
#pragma unroll
                    for (int m = 0; m < 4; m++) {
                        acc[r][m] = fmaf(qv.x, kvv[m].x, acc[r][m]);
                        acc[r][m] = fmaf(qv.y, kvv[m].y, acc[r][m]);
                        acc[r][m] = fmaf(qv.z, kvv[m].z, acc[r][m]);
                        acc[r][m] = fmaf(qv.w, kvv[m].w, acc[r][m]);
                    }
                }
            }

#pragma unroll
            for (int r = 0; r < 8; r++) {
                const int q = qbase + r;
                const float hq0 = H2S[q * 5 + 0];
                const float hq1 = H2S[q * 5 + 1];
                const float hq2 = H2S[q * 5 + 2];
                const float swq = SWS[q];
                const float mq  = MFS[q];

                float hh[4], val[4];
#pragma unroll
                for (int m = 0; m < 4; m++) {
                    hh[m] = fmaf(hq0, hk0[m], fmaf(hq1, hk1[m], hq2 * hk2[m]));
                    float a = acc[r][m] * hh[m];
                    val[m] = (a + ATTNW_SHIFT) * swq * swk[m] - ATTNW_SHIFT;
                }
                float mx = fmaxf(fmaxf(val[0], val[1]), fmaxf(val[2], val[3]));
#pragma unroll
                for (int sh = 16; sh > 0; sh >>= 1)
                    mx = fmaxf(mx, __shfl_xor_sync(0xffffffffu, mx, sh));
                float ssum = 0.0f;
#pragma unroll
                for (int m = 0; m < 4; m++) {
                    val[m] = __expf(val[m] - mx);
                    ssum += val[m];
                }
#pragma unroll
                for (int sh = 16; sh > 0; sh >>= 1)
                    ssum += __shfl_xor_sync(0xffffffffu, ssum, sh);
                const float rowc = __frcp_rn(ssum) * swq * mq * INV_SQRT3;

#pragma unroll
                for (int m = 0; m < 4; m++) {
                    float A = val[m] * rowc * kc[m] * hh[m];
                    // AS layout: q*144 + (k/32)*36 + (k%32), k = lane + 32m
                    AS[q * 144 + m * 36 + lane] = A;
                    int kk = lane + 32 * m;
                    if (h == 0) ASUM[q * 132 + kk] = weq * A;
                    else        ASUM[q * 132 + kk] += weq * A;
                }
            }
        }
        __syncwarp();   // AS warp-private: only STS->LDS visibility within warp needed

        // ============ phase c: accO += A[q][k-quarter] * P[k][o-set] (grouped gather) ======
        {
            const int rowbase = w * 8;
            const float* PSg = PS + g * 40;
#pragma unroll 2
            for (int k4 = 0; k4 < 8; k4++) {
                // P operands, row-invariant: k = g*32 + k4*4 + j
                u64 pP0[4], pP1[4];
#pragma unroll
                for (int j = 0; j < 4; j++) {
                    const float* prow = PSg + (k4 * 4 + j) * 160;
                    pP0[j] = pk2(prow[s],      prow[s + 8]);
                    pP1[j] = pk2(prow[s + 16], prow[s + 24]);
                }
#pragma unroll
                for (int r = 0; r < 8; r++) {
                    // one LDS.128 serves 4 groups' distinct 16B chunks (64B/wavefront)
                    const float4 a = *(const float4*)(AS + (rowbase + r) * 144 + g * 36 + k4 * 4);
                    u64 a0 = pk2(a.x, a.x);
                    u64 a1 = pk2(a.y, a.y);
                    u64 a2 = pk2(a.z, a.z);
                    u64 a3 = pk2(a.w, a.w);
                    fma2(accO0[r], a0, pP0[0]); fma2(accO1[r], a0, pP1[0]);
                    fma2(accO0[r], a1, pP0[1]); fma2(accO1[r], a1, pP1[1]);
                    fma2(accO0[r], a2, pP0[2]); fma2(accO1[r], a2, pP1[2]);
                    fma2(accO0[r], a3, pP0[3]); fma2(accO1[r], a3, pP1[3]);
                }
            }
        }
        __syncthreads();   // QS/KS/PS (and ASUM rows) reused next head / epilogue
    }

    // ---- epilogue: g2_out — bfly-reduce partials over k-quarter groups ----
    {
        const int rowbase = w * 8;
        const float bb0 = b_head[s];
        const float bb1 = b_head[s + 8];
        const float bb2 = b_head[s + 16];
        const float bb3 = b_head[s + 24];
#pragma unroll
        for (int r = 0; r < 8; r++) {
            float o0, o1, o2, o3;
            upk2(accO0[r], o0, o1);
            upk2(accO1[r], o2, o3);
#pragma unroll
            for (int sh = 8; sh <= 16; sh <<= 1) {
                o0 += __shfl_xor_sync(0xffffffffu, o0, sh);
                o1 += __shfl_xor_sync(0xffffffffu, o1, sh);
                o2 += __shfl_xor_sync(0xffffffffu, o2, sh);
                o3 += __shfl_xor_sync(0xffffffffu, o3, sh);
            }
            if (g == 0) {
                int q = rowbase + r;
                float* po = out + ((size_t)i * NNEI + q) * 32;
                po[s]      = o0 + bb0;
                po[s + 8]  = o1 + bb1;
                po[s + 16] = o2 + bb2;
                po[s + 24] = o3 + bb3;
            }
        }
    }

    // ---- epilogue: h2_out = ASUM @ h2 ----
    if (tid < 128) {
        const int q = tid;
        float s0 = 0.0f, s1 = 0.0f, s2 = 0.0f;
#pragma unroll 4
        for (int k4 = 0; k4 < 32; k4++) {
            float4 a = *(const float4*)(ASUM + q * 132 + k4 * 4);
            float av[4] = {a.x, a.y, a.z, a.w};
#pragma unroll
            for (int u = 0; u < 4; u++) {
                int k = k4 * 4 + u;
                s0 = fmaf(av[u], H2S[k * 5 + 0], s0);
                s1 = fmaf(av[u], H2S[k * 5 + 1], s1);
                s2 = fmaf(av[u], H2S[k * 5 + 2], s2);
            }
        }
        float* oh = out + (size_t)NLOC * NNEI * 32;
        size_t base = ((size_t)i * NNEI + q) * 3;
        oh[base + 0] = s0;
        oh[base + 1] = s1;
        oh[base + 2] = s2;
    }
}

extern "C" void kernel_launch(void* const* d_in, const int* in_sizes, int n_in,
                              void* d_out, int out_size) {
    const float* g2       = (const float*)d_in[0];
    const float* h2       = (const float*)d_in[1];
    const float* sw       = (const float*)d_in[2];
    const float* w_qk     = (const float*)d_in[3];
    const float* w_v      = (const float*)d_in[4];
    const float* w_head   = (const float*)d_in[5];
    const float* b_head   = (const float*)d_in[6];
    const float* w_eqhead = (const float*)d_in[7];
    const int*   nmask    = (const int*)d_in[8];
    float* out = (float*)d_out;

    precompute_W2_kernel<<<16, 256>>>(w_v, w_head);

    const size_t smem = (size_t)SM_FLOATS * sizeof(float);   // ~213.5 KB
    cudaFuncSetAttribute(repformer_kernel,
                         cudaFuncAttributeMaxDynamicSharedMemorySize, (int)smem);
    repformer_kernel<<<NLOC, 512, smem>>>(g2, h2, sw, w_qk, b_head, w_eqhead, nmask, out);
}

// round 7
// speedup vs baseline: 1.4245x; 1.1905x over previous
#include <cuda_runtime.h>
#include <cuda_bf16.h>

// RepformerLayer: nf=1, nloc=1024, nnei=128, ng2=32, nd=32, nh=4
// One CTA per location i (1024 CTAs, 512 threads = 16 warps, 8 rows/warp).
// R6: K-projection eliminated via M_h = Wq_h·Wk_h^T/sqrt(nd) precompute
//     (S = (g2·M_h)·g2^T). Phase a: 2 passes (T, P). Phase b K-operand = g2
//     (stride-36). FFMA2 m-pair packing in phase-b mainloop.
//     Keeps R5 phase-c grouped gather + bank-tuned AS/PS layouts.
//
// Algebra:
//   S_h    = g2 @ M_h @ g2^T,      M_h = Wq_h Wk_h^T / sqrt(nd)   (precomputed)
//   g2_out = b_head + sum_h A_h @ P_h,  P_h = g2 @ W2_h,  W2_h = w_v_h @ w_head_h
//   h2_out = (sum_h weq[h] * A_h) @ h2   (ASUM in smem)

#define NLOC 1024
#define NNEI 128
#define NG2  32
#define NH   4

#define INV_SQRT_ND 0.17677669529663687f   // 1/sqrt(32)
#define INV_SQRT3   0.57735026918962576f   // 1/sqrt(3)
#define ATTNW_SHIFT 20.0f

typedef unsigned long long u64;

__device__ __forceinline__ u64 pk2(float lo, float hi) {
    u64 r;
    asm("mov.b64 %0, {%1, %2};" : "=l"(r) : "f"(lo), "f"(hi));
    return r;
}
__device__ __forceinline__ void upk2(u64 v, float& lo, float& hi) {
    asm("mov.b64 {%0, %1}, %2;" : "=f"(lo), "=f"(hi) : "l"(v));
}
__device__ __forceinline__ void fma2(u64& d, u64 a, u64 b) {
    asm("fma.rn.f32x2 %0, %1, %2, %0;" : "+l"(d) : "l"(a), "l"(b));
}
__device__ __forceinline__ float hsum2(u64 v) {
    float lo, hi; upk2(v, lo, hi); return lo + hi;
}

// Precomputed W2[h][j][o] = sum_g w_v[j, g*4+h] * w_head[g*4+h, o]
// Precomputed M[h][j][jp] = (1/sqrt(nd)) * sum_d w_qk[j, d*8+h] * w_qk[jp, d*8+4+h]
__device__ float g_W2[NH][NG2][NG2];
__device__ float g_M[NH][NG2][NG2];

__global__ void precompute_kernel(const float* __restrict__ w_v,
                                  const float* __restrict__ w_head,
                                  const float* __restrict__ w_qk) {
    int t = blockIdx.x * blockDim.x + threadIdx.x;   // 8192 outputs
    if (t >= 2 * NH * NG2 * NG2) return;
    int o = t & 31;
    int j = (t >> 5) & 31;
    int h = (t >> 10) & 3;
    if (t < NH * NG2 * NG2) {
        float s = 0.0f;
#pragma unroll
        for (int g = 0; g < 32; g++)
            s = fmaf(w_v[j * 128 + g * 4 + h], w_head[(g * 4 + h) * 32 + o], s);
        g_W2[h][j][o] = s;
    } else {
        float s = 0.0f;
#pragma unroll
        for (int d = 0; d < 32; d++)
            s = fmaf(w_qk[j * 256 + d * 8 + h], w_qk[o * 256 + d * 8 + 4 + h], s);
        g_M[h][j][o] = s * INV_SQRT_ND;
    }
}

// ---- shared memory layout (floats) ----
// G2P  [128][36]    : 0      .. 4608    (pad 36: conflict-free .128 row reads)
// QS   [128][36]    : 4608   .. 9216
// PS   [32][4][40]  : 9216   .. 14336   (PS[k][o] at (k%32)*160 + (k/32)*40 + o)
// AS   [128][144]   : 14336  .. 32768   (A[q][k] at q*144 + (k/32)*36 + (k%32))
// ASUM [128][132]   : 32768  .. 49664
// H2S  [128][5]     : 49664  .. 50304
// SWS  [128]        : 50304  .. 50432
// MFS  [128]        : 50432  .. 50560
#define SM_FLOATS 50560

__global__ __launch_bounds__(512, 1)
void repformer_kernel(const float* __restrict__ g2,
                      const float* __restrict__ h2,
                      const float* __restrict__ sw,
                      const float* __restrict__ b_head,
                      const float* __restrict__ w_eqhead,
                      const int*   __restrict__ nlist_mask,
                      float* __restrict__ out) {
    extern __shared__ float sm[];
    float* G2P  = sm;
    float* QS   = sm + 4608;
    float* PS   = sm + 9216;
    float* AS   = sm + 14336;
    float* ASUM = sm + 32768;
    float* H2S  = sm + 49664;
    float* SWS  = sm + 50304;
    float* MFS  = sm + 50432;

    const int i    = blockIdx.x;
    const int tid  = threadIdx.x;
    const int lane = tid & 31;
    const int w    = tid >> 5;   // warp 0..15
    const int g    = lane >> 3;  // phase-c k-quarter group
    const int s    = lane & 7;

    // ---- load tile ----
    {
        const float4* src = (const float4*)(g2 + (size_t)i * NNEI * NG2);
        for (int v = tid; v < NNEI * NG2 / 4; v += 512) {
            int n  = v >> 3;
            int j4 = v & 7;
            *(float4*)(G2P + n * 36 + j4 * 4) = src[v];
        }
        if (tid < NNEI) {
            int n = tid;
            size_t base = ((size_t)i * NNEI + n);
            H2S[n * 5 + 0] = h2[base * 3 + 0];
            H2S[n * 5 + 1] = h2[base * 3 + 1];
            H2S[n * 5 + 2] = h2[base * 3 + 2];
            SWS[n] = sw[base];
            MFS[n] = nlist_mask[base] ? 1.0f : 0.0f;
        }
    }
    __syncthreads();

    // phase-c persistent accumulators: warp w owns rows w*8..+7;
    // lane (g,s) owns o in {s,s+8} (accO0) and {s+16,s+24} (accO1), k in [g*32, g*32+32)
    u64 accO0[8], accO1[8];
#pragma unroll
    for (int r = 0; r < 8; r++) { accO0[r] = 0ull; accO1[r] = 0ull; }

#pragma unroll 1
    for (int h = 0; h < NH; h++) {
        const float weq = w_eqhead[h];

        // ============ phase a: QS = g2 @ M_h,  PS = g2 @ W2_h ============
        // thread: column = lane, rows = w + 16*r (r=0..7). Packed weights + FFMA2.
#pragma unroll 1
        for (int m = 0; m < 2; m++) {
            u64 wreg[16];
            if (m == 0) {
#pragma unroll
                for (int t = 0; t < 16; t++)
                    wreg[t] = pk2(g_M[h][2 * t][lane], g_M[h][2 * t + 1][lane]);
            } else {
#pragma unroll
                for (int t = 0; t < 16; t++)
                    wreg[t] = pk2(g_W2[h][2 * t][lane], g_W2[h][2 * t + 1][lane]);
            }
            u64 acc[8];
#pragma unroll
            for (int r = 0; r < 8; r++) acc[r] = 0ull;
#pragma unroll
            for (int j4 = 0; j4 < 8; j4++) {
#pragma unroll
                for (int r = 0; r < 8; r++) {
                    ulonglong2 gv = *(const ulonglong2*)(G2P + (w + 16 * r) * 36 + j4 * 4);
                    fma2(acc[r], gv.x, wreg[2 * j4]);
                    fma2(acc[r], gv.y, wreg[2 * j4 + 1]);
                }
            }
            if (m == 0) {
#pragma unroll
                for (int r = 0; r < 8; r++)
                    QS[(w + 16 * r) * 36 + lane] = hsum2(acc[r]);
            } else {
#pragma unroll
                for (int r = 0; r < 8; r++) {
                    int row = w + 16 * r;
                    PS[(row & 31) * 160 + (row >> 5) * 40 + lane] = hsum2(acc[r]);
                }
            }
        }
        __syncthreads();

        // ============ phase b: S = T @ g2^T + scaling + softmax + masking ============
        // warp w owns rows w*8..w*8+7; lane owns k = lane + 32*m (K operand = G2P rows)
        {
            const int qbase = w * 8;

            float hk0[4], hk1[4], hk2[4], swk[4], kc[4];
#pragma unroll
            for (int m = 0; m < 4; m++) {
                int k = lane + 32 * m;
                hk0[m] = H2S[k * 5 + 0];
                hk1[m] = H2S[k * 5 + 1];
                hk2[m] = H2S[k * 5 + 2];
                swk[m] = SWS[k];
                kc[m]  = swk[m] * MFS[k];
            }

            // packed accumulators: pair 0 = (m0,m1), pair 1 = (m2,m3)
            u64 acc2[8][2];
#pragma unroll
            for (int r = 0; r < 8; r++) { acc2[r][0] = 0ull; acc2[r][1] = 0ull; }

#pragma unroll
            for (int d4 = 0; d4 < 8; d4++) {
                float4 kv[4];
#pragma unroll
                for (int m = 0; m < 4; m++)
                    kv[m] = *(const float4*)(G2P + (lane + 32 * m) * 36 + d4 * 4);
                u64 kp0x = pk2(kv[0].x, kv[1].x), kp1x = pk2(kv[2].x, kv[3].x);
                u64 kp0y = pk2(kv[0].y, kv[1].y), kp1y = pk2(kv[2].y, kv[3].y);
                u64 kp0z = pk2(kv[0].z, kv[1].z), kp1z = pk2(kv[2].z, kv[3].z);
                u64 kp0w = pk2(kv[0].w, kv[1].w), kp1w = pk2(kv[2].w, kv[3].w);
#pragma unroll
                for (int r = 0; r < 8; r++) {
                    float4 qv = *(const float4*)(QS + (qbase + r) * 36 + d4 * 4);
                    u64 qx = pk2(qv.x, qv.x);
                    u64 qy = pk2(qv.y, qv.y);
                    u64 qz = pk2(qv.z, qv.z);
                    u64 qw = pk2(qv.w, qv.w);
                    fma2(acc2[r][0], qx, kp0x); fma2(acc2[r][1], qx, kp1x);
                    fma2(acc2[r][0], qy, kp0y); fma2(acc2[r][1], qy, kp1y);
                    fma2(acc2[r][0], qz, kp0z); fma2(acc2[r][1], qz, kp1z);
                    fma2(acc2[r][0], qw, kp0w); fma2(acc2[r][1], qw, kp1w);
                }
            }

#pragma unroll
            for (int r = 0; r < 8; r++) {
                const int q = qbase + r;
                const float hq0 = H2S[q * 5 + 0];
                const float hq1 = H2S[q * 5 + 1];
                const float hq2 = H2S[q * 5 + 2];
                const float swq = SWS[q];
                const float mq  = MFS[q];

                float sc[4];
                upk2(acc2[r][0], sc[0], sc[1]);
                upk2(acc2[r][1], sc[2], sc[3]);

                float hh[4], val[4];
#pragma unroll
                for (int m = 0; m < 4; m++) {
                    hh[m] = fmaf(hq0, hk0[m], fmaf(hq1, hk1[m], hq2 * hk2[m]));
                    float a = sc[m] * hh[m];
                    val[m] = (a + ATTNW_SHIFT) * swq * swk[m] - ATTNW_SHIFT;
                }
                float mx = fmaxf(fmaxf(val[0], val[1]), fmaxf(val[2], val[3]));
#pragma unroll
                for (int sh = 16; sh > 0; sh >>= 1)
                    mx = fmaxf(mx, __shfl_xor_sync(0xffffffffu, mx, sh));
                float ssum = 0.0f;
#pragma unroll
                for (int m = 0; m < 4; m++) {
                    val[m] = __expf(val[m] - mx);
                    ssum += val[m];
                }
#pragma unroll
                for (int sh = 16; sh > 0; sh >>= 1)
                    ssum += __shfl_xor_sync(0xffffffffu, ssum, sh);
                const float rowc = __frcp_rn(ssum) * swq * mq * INV_SQRT3;

#pragma unroll
                for (int m = 0; m < 4; m++) {
                    float A = val[m] * rowc * kc[m] * hh[m];
                    // AS layout: q*144 + (k/32)*36 + (k%32), k = lane + 32m
                    AS[q * 144 + m * 36 + lane] = A;
                    int kk = lane + 32 * m;
                    if (h == 0) ASUM[q * 132 + kk] = weq * A;
                    else        ASUM[q * 132 + kk] += weq * A;
                }
            }
        }
        __syncwarp();   // AS warp-private: only STS->LDS visibility within warp needed

        // ============ phase c: accO += A[q][k-quarter] * P[k][o-set] (grouped gather) ======
        {
            const int rowbase = w * 8;
            const float* PSg = PS + g * 40;
#pragma unroll 2
            for (int k4 = 0; k4 < 8; k4++) {
                // P operands, row-invariant: k = g*32 + k4*4 + j
                u64 pP0[4], pP1[4];
#pragma unroll
                for (int j = 0; j < 4; j++) {
                    const float* prow = PSg + (k4 * 4 + j) * 160;
                    pP0[j] = pk2(prow[s],      prow[s + 8]);
                    pP1[j] = pk2(prow[s + 16], prow[s + 24]);
                }
#pragma unroll
                for (int r = 0; r < 8; r++) {
                    // one LDS.128 serves 4 groups' distinct 16B chunks
                    const float4 a = *(const float4*)(AS + (rowbase + r) * 144 + g * 36 + k4 * 4);
                    u64 a0 = pk2(a.x, a.x);
                    u64 a1 = pk2(a.y, a.y);
                    u64 a2 = pk2(a.z, a.z);
                    u64 a3 = pk2(a.w, a.w);
                    fma2(accO0[r], a0, pP0[0]); fma2(accO1[r], a0, pP1[0]);
                    fma2(accO0[r], a1, pP0[1]); fma2(accO1[r], a1, pP1[1]);
                    fma2(accO0[r], a2, pP0[2]); fma2(accO1[r], a2, pP1[2]);
                    fma2(accO0[r], a3, pP0[3]); fma2(accO1[r], a3, pP1[3]);
                }
            }
        }
        __syncthreads();   // QS/PS reused next head
    }

    // ---- epilogue: g2_out — bfly-reduce partials over k-quarter groups ----
    {
        const int rowbase = w * 8;
        const float bb0 = b_head[s];
        const float bb1 = b_head[s + 8];
        const float bb2 = b_head[s + 16];
        const float bb3 = b_head[s + 24];
#pragma unroll
        for (int r = 0; r < 8; r++) {
            float o0, o1, o2, o3;
            upk2(accO0[r], o0, o1);
            upk2(accO1[r], o2, o3);
#pragma unroll
            for (int sh = 8; sh <= 16; sh <<= 1) {
                o0 += __shfl_xor_sync(0xffffffffu, o0, sh);
                o1 += __shfl_xor_sync(0xffffffffu, o1, sh);
                o2 += __shfl_xor_sync(0xffffffffu, o2, sh);
                o3 += __shfl_xor_sync(0xffffffffu, o3, sh);
            }
            if (g == 0) {
                int q = rowbase + r;
                float* po = out + ((size_t)i * NNEI + q) * 32;
                po[s]      = o0 + bb0;
                po[s + 8]  = o1 + bb1;
                po[s + 16] = o2 + bb2;
                po[s + 24] = o3 + bb3;
            }
        }
    }

    // ---- epilogue: h2_out = ASUM @ h2 ----
    if (tid < 128) {
        const int q = tid;
        float s0 = 0.0f, s1 = 0.0f, s2 = 0.0f;
#pragma unroll 4
        for (int k4 = 0; k4 < 32; k4++) {
            float4 a = *(const float4*)(ASUM + q * 132 + k4 * 4);
            float av[4] = {a.x, a.y, a.z, a.w};
#pragma unroll
            for (int u = 0; u < 4; u++) {
                int k = k4 * 4 + u;
                s0 = fmaf(av[u], H2S[k * 5 + 0], s0);
                s1 = fmaf(av[u], H2S[k * 5 + 1], s1);
                s2 = fmaf(av[u], H2S[k * 5 + 2], s2);
            }
        }
        float* oh = out + (size_t)NLOC * NNEI * 32;
        size_t base = ((size_t)i * NNEI + q) * 3;
        oh[base + 0] = s0;
        oh[base + 1] = s1;
        oh[base + 2] = s2;
    }
}

extern "C" void kernel_launch(void* const* d_in, const int* in_sizes, int n_in,
                              void* d_out, int out_size) {
    const float* g2       = (const float*)d_in[0];
    const float* h2       = (const float*)d_in[1];
    const float* sw       = (const float*)d_in[2];
    const float* w_qk     = (const float*)d_in[3];
    const float* w_v      = (const float*)d_in[4];
    const float* w_head   = (const float*)d_in[5];
    const float* b_head   = (const float*)d_in[6];
    const float* w_eqhead = (const float*)d_in[7];
    const int*   nmask    = (const int*)d_in[8];
    float* out = (float*)d_out;

    precompute_kernel<<<32, 256>>>(w_v, w_head, w_qk);

    const size_t smem = (size_t)SM_FLOATS * sizeof(float);   // ~197.5 KB
    cudaFuncSetAttribute(repformer_kernel,
                         cudaFuncAttributeMaxDynamicSharedMemorySize, (int)smem);
    repformer_kernel<<<NLOC, 512, smem>>>(g2, h2, sw, b_head, w_eqhead, nmask, out);
}